// round 2
// baseline (speedup 1.0000x reference)
#include <cuda_runtime.h>

#define BATCH 16
#define SEQ 512
#define DIN 768
#define HDIM 256
#define IDIM 512
#define NSTATE 16
#define RDIM 16
#define KCONV 4
#define NLAYER 2
#define ROWS (BATCH*SEQ)   // 8192
#define KAN1K (DIN*9)      // 6912

// ---------------- scratch (static device globals; no allocation) ----------------
__device__ float g_h[ROWS*HDIM];
__device__ float g_xr[ROWS*HDIM];
__device__ float g_proj[ROWS*2*IDIM];
__device__ float g_u[ROWS*IDIM];
__device__ float g_dt[ROWS*IDIM];
__device__ float g_y[ROWS*IDIM];
__device__ float g_ssm[ROWS*48];
__device__ float g_w1[KAN1K*HDIM];               // combined KAN1 weights [kk][col]
__device__ float g_wti[NLAYER*HDIM*2*IDIM];      // in_proj^T  [K=256][N=1024]
__device__ float g_wto[NLAYER*IDIM*HDIM];        // out_proj^T [K=512][N=256]

// ---------------- math helpers (FMA-pipe exp; no MUFU in hot loops) ----------------
__device__ __forceinline__ float fexp(float x) {
    float y = x * 1.4426950408889634f;
    y = fminf(fmaxf(y, -125.f), 125.f);
    float f = floorf(y);
    float r = y - f;
    float p = 1.5403989e-4f;
    p = fmaf(p, r, 1.3333558e-3f);
    p = fmaf(p, r, 9.6181291e-3f);
    p = fmaf(p, r, 5.5504109e-2f);
    p = fmaf(p, r, 2.4022651e-1f);
    p = fmaf(p, r, 6.9314718e-1f);
    p = fmaf(p, r, 1.0f);
    return p * __int_as_float(((int)f + 127) << 23);
}

__device__ __forceinline__ float fsilu(float x) {
    return x / (1.0f + fexp(-x));
}

// Cubic B-spline basis, grid_size=5, order=3, knots t_j = 0.4*(j-3)-1, j=0..11
__device__ __forceinline__ void kan_basis(float x, float bs[8]) {
    float b0[11];
#pragma unroll
    for (int j = 0; j < 11; j++) {
        float t0 = 0.4f * (float)(j - 3) - 1.0f;
        float t1 = 0.4f * (float)(j - 2) - 1.0f;
        b0[j] = (x >= t0 && x < t1) ? 1.0f : 0.0f;
    }
    float b1[10];
#pragma unroll
    for (int j = 0; j < 10; j++) {
        float tj  = 0.4f * (float)(j - 3) - 1.0f;
        float tj2 = 0.4f * (float)(j - 1) - 1.0f;
        b1[j] = (x - tj) * 2.5f * b0[j] + (tj2 - x) * 2.5f * b0[j + 1];
    }
    float b2[9];
#pragma unroll
    for (int j = 0; j < 9; j++) {
        float tj  = 0.4f * (float)(j - 3) - 1.0f;
        float tj3 = 0.4f * (float)(j)     - 1.0f;
        b2[j] = (x - tj) * 1.25f * b1[j] + (tj3 - x) * 1.25f * b1[j + 1];
    }
#pragma unroll
    for (int j = 0; j < 8; j++) {
        float tj  = 0.4f * (float)(j - 3) - 1.0f;
        float tj4 = 0.4f * (float)(j + 1) - 1.0f;
        bs[j] = (x - tj) * 0.83333333333f * b2[j] + (tj4 - x) * 0.83333333333f * b2[j + 1];
    }
}

// ---------------- weight prep ----------------
// combined KAN1 weight: W[kk=i*9+c][col]; c=0 -> base, c=1..8 -> spline_w*spline_s
__global__ void kanw_kernel(const float* __restrict__ bw, const float* __restrict__ sw,
                            const float* __restrict__ ss, float* __restrict__ out) {
    int idx = blockIdx.x * 256 + threadIdx.x;
    if (idx >= KAN1K * HDIM) return;
    int col = idx & 255;
    int kk = idx >> 8;
    int i = kk / 9, c = kk - i * 9;
    float v;
    if (c == 0) v = bw[col * DIN + i];
    else        v = sw[(col * DIN + i) * 8 + (c - 1)] * ss[col * DIN + i];
    out[kk * HDIM + col] = v;
}

__global__ void transpose_kernel(const float* __restrict__ in, float* __restrict__ out,
                                 int N, int K) {
    int idx = blockIdx.x * 256 + threadIdx.x;
    if (idx >= N * K) return;
    int n = idx % N, k = idx / N;
    out[k * N + n] = in[n * K + k];
}

// ---------------- KAN layer 1 (activation-expanded GEMM) ----------------
// 128x64 tile, chunk of 4 inputs (36 k), 256 threads, 8x4 frags
__global__ __launch_bounds__(256) void kan1_kernel(const float* __restrict__ X,
                                                   const float* __restrict__ Wc,
                                                   float* __restrict__ H) {
    __shared__ __align__(16) float sA[36][132];
    __shared__ __align__(16) float sW[36][68];
    int row0 = blockIdx.y * 128;
    int col0 = blockIdx.x * 64;
    int tid = threadIdx.x;
    int tr = tid >> 4, tc = tid & 15;
    float acc[8][4];
#pragma unroll
    for (int a = 0; a < 8; a++)
#pragma unroll
        for (int b = 0; b < 4; b++) acc[a][b] = 0.f;

    for (int i0 = 0; i0 < DIN; i0 += 4) {
        __syncthreads();
        // activations: 128 rows x 4 inputs -> 36 k rows
#pragma unroll
        for (int t = 0; t < 2; t++) {
            int p = tid + t * 256;       // 0..511
            int r = p >> 2, il = p & 3;
            float x = X[(row0 + r) * DIN + i0 + il];
            float bs[8];
            kan_basis(x, bs);
            sA[il * 9 + 0][r] = fsilu(x);
#pragma unroll
            for (int k = 0; k < 8; k++) sA[il * 9 + 1 + k][r] = bs[k];
        }
        // weights: 36 x 64
#pragma unroll
        for (int t = 0; t < 9; t++) {
            int idx = tid + t * 256;     // 0..2303
            int kk = idx >> 6, c = idx & 63;
            sW[kk][c] = Wc[(i0 * 9 + kk) * HDIM + col0 + c];
        }
        __syncthreads();
#pragma unroll
        for (int kk = 0; kk < 36; kk++) {
            float4 a0 = *(const float4*)&sA[kk][tr * 8];
            float4 a1 = *(const float4*)&sA[kk][tr * 8 + 4];
            float4 w  = *(const float4*)&sW[kk][tc * 4];
            float av[8] = {a0.x, a0.y, a0.z, a0.w, a1.x, a1.y, a1.z, a1.w};
            float wv[4] = {w.x, w.y, w.z, w.w};
#pragma unroll
            for (int ii = 0; ii < 8; ii++)
#pragma unroll
                for (int jj = 0; jj < 4; jj++)
                    acc[ii][jj] = fmaf(av[ii], wv[jj], acc[ii][jj]);
        }
    }
#pragma unroll
    for (int ii = 0; ii < 8; ii++) {
        float4 v = make_float4(acc[ii][0], acc[ii][1], acc[ii][2], acc[ii][3]);
        *(float4*)&H[(row0 + tr * 8 + ii) * HDIM + col0 + tc * 4] = v;
    }
}

// ---------------- generic GEMM: C[M,N] = A[M,K] @ Wt[K,N] (+C if RESID) ----------------
template <int RESID>
__global__ __launch_bounds__(256) void gemm_kernel(const float* __restrict__ A,
                                                   const float* __restrict__ Wt,
                                                   float* __restrict__ C,
                                                   int M, int N, int K) {
    __shared__ __align__(16) float sA[16][132];
    __shared__ __align__(16) float sW[16][68];
    int row0 = blockIdx.y * 128;
    int col0 = blockIdx.x * 64;
    int tid = threadIdx.x;
    int tr = tid >> 4, tc = tid & 15;
    float acc[8][4];
#pragma unroll
    for (int a = 0; a < 8; a++)
#pragma unroll
        for (int b = 0; b < 4; b++) acc[a][b] = 0.f;

    for (int k0 = 0; k0 < K; k0 += 16) {
        __syncthreads();
#pragma unroll
        for (int t = 0; t < 8; t++) {
            int idx = tid + t * 256;     // 0..2047
            int r = idx >> 4, kk = idx & 15;
            sA[kk][r] = A[(row0 + r) * K + k0 + kk];
        }
#pragma unroll
        for (int t = 0; t < 4; t++) {
            int idx = tid + t * 256;     // 0..1023
            int kk = idx >> 6, c = idx & 63;
            sW[kk][c] = Wt[(k0 + kk) * N + col0 + c];
        }
        __syncthreads();
#pragma unroll
        for (int kk = 0; kk < 16; kk++) {
            float4 a0 = *(const float4*)&sA[kk][tr * 8];
            float4 a1 = *(const float4*)&sA[kk][tr * 8 + 4];
            float4 w  = *(const float4*)&sW[kk][tc * 4];
            float av[8] = {a0.x, a0.y, a0.z, a0.w, a1.x, a1.y, a1.z, a1.w};
            float wv[4] = {w.x, w.y, w.z, w.w};
#pragma unroll
            for (int ii = 0; ii < 8; ii++)
#pragma unroll
                for (int jj = 0; jj < 4; jj++)
                    acc[ii][jj] = fmaf(av[ii], wv[jj], acc[ii][jj]);
        }
    }
#pragma unroll
    for (int ii = 0; ii < 8; ii++) {
        float4* p = (float4*)&C[(row0 + tr * 8 + ii) * N + col0 + tc * 4];
        float4 v = make_float4(acc[ii][0], acc[ii][1], acc[ii][2], acc[ii][3]);
        if (RESID) {
            float4 o = *p;
            v.x += o.x; v.y += o.y; v.z += o.z; v.w += o.w;
        }
        *p = v;
    }
}

// ---------------- norms ----------------
__device__ __forceinline__ float block_sum256(float v, float* red) {
    int tid = threadIdx.x;
#pragma unroll
    for (int o = 16; o; o >>= 1) v += __shfl_xor_sync(0xffffffffu, v, o);
    if ((tid & 31) == 0) red[tid >> 5] = v;
    __syncthreads();
    if (tid < 32) {
        float t = (tid < 8) ? red[tid] : 0.f;
#pragma unroll
        for (int o = 4; o; o >>= 1) t += __shfl_xor_sync(0xffffffffu, t, o);
        if (tid == 0) red[0] = t;
    }
    __syncthreads();
    float r = red[0];
    __syncthreads();
    return r;
}

__global__ __launch_bounds__(256) void layernorm_kernel(float* __restrict__ H,
                                                        const float* __restrict__ g,
                                                        const float* __restrict__ b) {
    __shared__ float red[8];
    int row = blockIdx.x, tid = threadIdx.x;
    float v = H[row * HDIM + tid];
    float mean = block_sum256(v, red) * (1.0f / HDIM);
    float d = v - mean;
    float var = block_sum256(d * d, red) * (1.0f / HDIM);
    H[row * HDIM + tid] = d * rsqrtf(var + 1e-5f) * g[tid] + b[tid];
}

__global__ __launch_bounds__(256) void rmsnorm_kernel(const float* __restrict__ In,
                                                      const float* __restrict__ w,
                                                      float* __restrict__ Out) {
    __shared__ float red[8];
    int row = blockIdx.x, tid = threadIdx.x;
    float v = In[row * HDIM + tid];
    float ms = block_sum256(v * v, red) * (1.0f / HDIM);
    Out[row * HDIM + tid] = w[tid] * v * rsqrtf(ms + 1e-5f);
}

// ---------------- mamba pieces ----------------
__global__ __launch_bounds__(512) void conv_silu_kernel(const float* __restrict__ proj,
                                                        const float* __restrict__ cw,
                                                        const float* __restrict__ cb,
                                                        float* __restrict__ u) {
    int i = threadIdx.x;
    int bl = blockIdx.x;
    int b = bl >> 9, l = bl & 511;
    float acc = cb[i];
#pragma unroll
    for (int k = 0; k < KCONV; k++) {
        int ll = l - 3 + k;
        if (ll >= 0)
            acc = fmaf(proj[((b << 9) + ll) * (2 * IDIM) + i], cw[i * KCONV + k], acc);
    }
    u[bl * IDIM + i] = fsilu(acc);
}

// ssm[row, 0:48] = u[row,:] @ xw[48,512]^T ; warp per row-group, 6 outs per warp
__global__ __launch_bounds__(256) void xproj_kernel(const float* __restrict__ u,
                                                    const float* __restrict__ xw,
                                                    float* __restrict__ ssm) {
    int row = blockIdx.x;
    int tid = threadIdx.x;
    int w = tid >> 5, lane = tid & 31;
    float part[6] = {0, 0, 0, 0, 0, 0};
    const float* ur = u + row * IDIM;
    for (int k = lane; k < IDIM; k += 32) {
        float uv = ur[k];
#pragma unroll
        for (int j = 0; j < 6; j++)
            part[j] = fmaf(uv, xw[(w * 6 + j) * IDIM + k], part[j]);
    }
#pragma unroll
    for (int j = 0; j < 6; j++) {
#pragma unroll
        for (int o = 16; o; o >>= 1) part[j] += __shfl_xor_sync(0xffffffffu, part[j], o);
    }
    if (lane == 0) {
#pragma unroll
        for (int j = 0; j < 6; j++) ssm[row * 48 + w * 6 + j] = part[j];
    }
}

__global__ __launch_bounds__(256) void dt_kernel(const float* __restrict__ ssm,
                                                 const float* __restrict__ dtw,
                                                 const float* __restrict__ dtb,
                                                 float* __restrict__ dt) {
    int idx = blockIdx.x * 256 + threadIdx.x;
    int i = idx & (IDIM - 1);
    int row = idx >> 9;
    float z = dtb[i];
#pragma unroll
    for (int r = 0; r < RDIM; r++)
        z = fmaf(ssm[row * 48 + r], dtw[i * RDIM + r], z);
    float sp = (z > 20.f) ? z : log1pf(fexp(z));
    dt[idx] = sp;
}

// scan: 16 threads per (b,i) channel; sequential over L
__global__ __launch_bounds__(256) void scan_kernel(const float* __restrict__ dt,
                                                   const float* __restrict__ u,
                                                   const float* __restrict__ ssm,
                                                   const float* __restrict__ proj,
                                                   const float* __restrict__ alog,
                                                   const float* __restrict__ Dp,
                                                   float* __restrict__ y) {
    int idx = blockIdx.x * 256 + threadIdx.x;
    int n = idx & 15;
    int ch = idx >> 4;
    int i = ch & (IDIM - 1);
    int b = ch >> 9;
    float A = -fexp(alog[i * NSTATE + n]);
    float Dv = Dp[i];
    float s = 0.f;
    int base = b * SEQ;
    for (int l = 0; l < SEQ; l++) {
        int row = base + l;
        float dtv = dt[row * IDIM + i];
        float uv = u[row * IDIM + i];
        float Bv = ssm[row * 48 + 16 + n];
        float Cv = ssm[row * 48 + 32 + n];
        float dA = fexp(dtv * A);
        s = fmaf(s, dA, dtv * uv * Bv);
        float part = s * Cv;
        part += __shfl_xor_sync(0xffffffffu, part, 8);
        part += __shfl_xor_sync(0xffffffffu, part, 4);
        part += __shfl_xor_sync(0xffffffffu, part, 2);
        part += __shfl_xor_sync(0xffffffffu, part, 1);
        if (n == 0) {
            float g = proj[row * (2 * IDIM) + IDIM + i];
            y[row * IDIM + i] = (part + uv * Dv) * fsilu(g);
        }
    }
}

// ---------------- pooling + KAN head ----------------
__global__ __launch_bounds__(256) void pool_kernel(const float* __restrict__ xr,
                                                   float* __restrict__ emb) {
    int b = blockIdx.x, tid = threadIdx.x;
    float sm = 0.f, mx = -3.402823466e38f;
    for (int l = 0; l < SEQ; l++) {
        float v = xr[(b * SEQ + l) * HDIM + tid];
        sm += v;
        mx = fmaxf(mx, v);
    }
    emb[b * 512 + tid] = sm * (1.0f / SEQ);
    emb[b * 512 + 256 + tid] = mx;
}

__global__ __launch_bounds__(256) void kan2_kernel(const float* __restrict__ emb,
                                                   const float* __restrict__ bw,
                                                   const float* __restrict__ sw,
                                                   const float* __restrict__ ss,
                                                   float* __restrict__ logits) {
    __shared__ float red[2][256];
    int b = blockIdx.x, tid = threadIdx.x;
    float p0 = 0.f, p1 = 0.f;
#pragma unroll
    for (int t = 0; t < 2; t++) {
        int i = tid + t * 256;
        float x = emb[b * 512 + i];
        float sl = fsilu(x);
        float bs[8];
        kan_basis(x, bs);
        float a0 = sl * bw[i];
        float a1 = sl * bw[512 + i];
        float s0 = ss[i], s1 = ss[512 + i];
#pragma unroll
        for (int k = 0; k < 8; k++) {
            a0 = fmaf(bs[k] * s0, sw[i * 8 + k], a0);
            a1 = fmaf(bs[k] * s1, sw[(512 + i) * 8 + k], a1);
        }
        p0 += a0;
        p1 += a1;
    }
    red[0][tid] = p0;
    red[1][tid] = p1;
    __syncthreads();
    for (int s = 128; s > 0; s >>= 1) {
        if (tid < s) {
            red[0][tid] += red[0][tid + s];
            red[1][tid] += red[1][tid + s];
        }
        __syncthreads();
    }
    if (tid == 0) {
        logits[b * 2 + 0] = red[0][0];
        logits[b * 2 + 1] = red[1][0];
    }
}

// ---------------- launch ----------------
extern "C" void kernel_launch(void* const* d_in, const int* in_sizes, int n_in,
                              void* d_out, int out_size) {
    const float* x         = (const float*)d_in[0];
    const float* base_w1   = (const float*)d_in[1];
    const float* spline_w1 = (const float*)d_in[2];
    const float* spline_s1 = (const float*)d_in[3];
    const float* ln_g      = (const float*)d_in[4];
    const float* ln_b      = (const float*)d_in[5];
    const float* norm_w    = (const float*)d_in[6];
    const float* in_proj_w = (const float*)d_in[7];
    const float* conv_w    = (const float*)d_in[8];
    const float* conv_b    = (const float*)d_in[9];
    const float* x_proj_w  = (const float*)d_in[10];
    const float* dt_w      = (const float*)d_in[11];
    const float* dt_b      = (const float*)d_in[12];
    const float* A_log     = (const float*)d_in[13];
    const float* Dp        = (const float*)d_in[14];
    const float* out_proj_w= (const float*)d_in[15];
    const float* normf_w   = (const float*)d_in[16];
    const float* base_w2   = (const float*)d_in[17];
    const float* spline_w2 = (const float*)d_in[18];
    const float* spline_s2 = (const float*)d_in[19];
    float* out = (float*)d_out;

    float *p_h, *p_xr, *p_proj, *p_u, *p_dt, *p_y, *p_ssm, *p_w1, *p_wti, *p_wto;
    cudaGetSymbolAddress((void**)&p_h, g_h);
    cudaGetSymbolAddress((void**)&p_xr, g_xr);
    cudaGetSymbolAddress((void**)&p_proj, g_proj);
    cudaGetSymbolAddress((void**)&p_u, g_u);
    cudaGetSymbolAddress((void**)&p_dt, g_dt);
    cudaGetSymbolAddress((void**)&p_y, g_y);
    cudaGetSymbolAddress((void**)&p_ssm, g_ssm);
    cudaGetSymbolAddress((void**)&p_w1, g_w1);
    cudaGetSymbolAddress((void**)&p_wti, g_wti);
    cudaGetSymbolAddress((void**)&p_wto, g_wto);

    // weight prep
    kanw_kernel<<<(KAN1K * HDIM + 255) / 256, 256>>>(base_w1, spline_w1, spline_s1, p_w1);
    for (int l = 0; l < NLAYER; l++) {
        transpose_kernel<<<(2 * IDIM * HDIM + 255) / 256, 256>>>(
            in_proj_w + l * 2 * IDIM * HDIM, p_wti + l * HDIM * 2 * IDIM, 2 * IDIM, HDIM);
        transpose_kernel<<<(HDIM * IDIM + 255) / 256, 256>>>(
            out_proj_w + l * HDIM * IDIM, p_wto + l * IDIM * HDIM, HDIM, IDIM);
    }

    // KAN1 + layernorm
    kan1_kernel<<<dim3(HDIM / 64, ROWS / 128), 256>>>(x, p_w1, p_h);
    layernorm_kernel<<<ROWS, 256>>>(p_h, ln_g, ln_b);

    // Mamba blocks
    for (int l = 0; l < NLAYER; l++) {
        rmsnorm_kernel<<<ROWS, 256>>>(p_h, norm_w + l * HDIM, p_xr);
        gemm_kernel<0><<<dim3(2 * IDIM / 64, ROWS / 128), 256>>>(
            p_xr, p_wti + l * HDIM * 2 * IDIM, p_proj, ROWS, 2 * IDIM, HDIM);
        conv_silu_kernel<<<ROWS, IDIM>>>(p_proj, conv_w + l * IDIM * KCONV,
                                         conv_b + l * IDIM, p_u);
        xproj_kernel<<<ROWS, 256>>>(p_u, x_proj_w + l * 48 * IDIM, p_ssm);
        dt_kernel<<<(ROWS * IDIM) / 256, 256>>>(p_ssm, dt_w + l * IDIM * RDIM,
                                                dt_b + l * IDIM, p_dt);
        scan_kernel<<<(BATCH * IDIM * NSTATE) / 256, 256>>>(
            p_dt, p_u, p_ssm, p_proj, A_log + l * IDIM * NSTATE, Dp + l * IDIM, p_y);
        gemm_kernel<1><<<dim3(HDIM / 64, ROWS / 128), 256>>>(
            p_y, p_wto + l * IDIM * HDIM, p_h, ROWS, HDIM, IDIM);
    }

    // final norm, pool, head
    rmsnorm_kernel<<<ROWS, 256>>>(p_h, normf_w, p_xr);
    pool_kernel<<<BATCH, 256>>>(p_xr, out + 32);
    kan2_kernel<<<BATCH, 256>>>(out + 32, base_w2, spline_w2, spline_s2, out);
}

// round 5
// speedup vs baseline: 1.2063x; 1.2063x over previous
#include <cuda_runtime.h>
#include <cuda_bf16.h>
#include <cstdint>

#define BATCH 16
#define SEQ 512
#define DIN 768
#define HDIM 256
#define IDIM 512
#define NSTATE 16
#define RDIM 16
#define KCONV 4
#define NLAYER 2
#define ROWS (BATCH*SEQ)   // 8192
#define KAN1K (DIN*9)      // 6912
#define SSMW 128           // padded x_proj output stride (48 real)

// ---------------- scratch (static device globals; no allocation) ----------------
__device__ float g_h[ROWS*HDIM];
__device__ float g_xr[ROWS*HDIM];
__device__ float g_proj[ROWS*2*IDIM];
__device__ float g_u[ROWS*IDIM];
__device__ float g_dt[ROWS*IDIM];
__device__ float g_ssm[ROWS*SSMW];
// bf16 hi/lo operand buffers
__device__ __nv_bfloat16 g_Eh[(size_t)ROWS*KAN1K];
__device__ __nv_bfloat16 g_El[(size_t)ROWS*KAN1K];
__device__ __nv_bfloat16 g_W1h[(size_t)HDIM*KAN1K];
__device__ __nv_bfloat16 g_W1l[(size_t)HDIM*KAN1K];
__device__ __nv_bfloat16 g_IPh[NLAYER*2*IDIM*HDIM];
__device__ __nv_bfloat16 g_IPl[NLAYER*2*IDIM*HDIM];
__device__ __nv_bfloat16 g_OPh[NLAYER*HDIM*IDIM];
__device__ __nv_bfloat16 g_OPl[NLAYER*HDIM*IDIM];
__device__ __nv_bfloat16 g_XPh[NLAYER*SSMW*IDIM];
__device__ __nv_bfloat16 g_XPl[NLAYER*SSMW*IDIM];
__device__ __nv_bfloat16 g_Xh[ROWS*HDIM];
__device__ __nv_bfloat16 g_Xl[ROWS*HDIM];
__device__ __nv_bfloat16 g_Uh[ROWS*IDIM];
__device__ __nv_bfloat16 g_Ul[ROWS*IDIM];
__device__ __nv_bfloat16 g_Yh[ROWS*IDIM];
__device__ __nv_bfloat16 g_Yl[ROWS*IDIM];

// ---------------- math helpers (FMA-pipe; no MUFU in hot loops) ----------------
__device__ __forceinline__ float fexp(float x) {
    float y = x * 1.4426950408889634f;
    y = fminf(fmaxf(y, -125.f), 125.f);
    float f = floorf(y);
    float r = y - f;
    float p = 1.5403989e-4f;
    p = fmaf(p, r, 1.3333558e-3f);
    p = fmaf(p, r, 9.6181291e-3f);
    p = fmaf(p, r, 5.5504109e-2f);
    p = fmaf(p, r, 2.4022651e-1f);
    p = fmaf(p, r, 6.9314718e-1f);
    p = fmaf(p, r, 1.0f);
    return p * __int_as_float(((int)f + 127) << 23);
}
__device__ __forceinline__ float fsilu(float x) { return x / (1.0f + fexp(-x)); }

// FMA-pipe natural log for softplus
__device__ __forceinline__ float fln(float w) {
    int e = (__float_as_int(w) >> 23) - 127;
    float m = __int_as_float((__float_as_int(w) & 0x007FFFFF) | 0x3F800000);
    if (m > 1.4142135f) { m *= 0.5f; e += 1; }
    float t = m - 1.0f;
    float p = -1.0f / 12.0f;
    p = fmaf(p, t,  1.0f / 11.0f);
    p = fmaf(p, t, -1.0f / 10.0f);
    p = fmaf(p, t,  1.0f / 9.0f);
    p = fmaf(p, t, -1.0f / 8.0f);
    p = fmaf(p, t,  1.0f / 7.0f);
    p = fmaf(p, t, -1.0f / 6.0f);
    p = fmaf(p, t,  1.0f / 5.0f);
    p = fmaf(p, t, -0.25f);
    p = fmaf(p, t,  1.0f / 3.0f);
    p = fmaf(p, t, -0.5f);
    p = fmaf(p, t,  1.0f);
    p = p * t;
    return fmaf((float)e, 0.6931471805599453f, p);
}

// Cubic B-spline basis, grid_size=5, order=3
__device__ __forceinline__ void kan_basis(float x, float bs[8]) {
    float b0[11];
#pragma unroll
    for (int j = 0; j < 11; j++) {
        float t0 = 0.4f * (float)(j - 3) - 1.0f;
        float t1 = 0.4f * (float)(j - 2) - 1.0f;
        b0[j] = (x >= t0 && x < t1) ? 1.0f : 0.0f;
    }
    float b1[10];
#pragma unroll
    for (int j = 0; j < 10; j++) {
        float tj  = 0.4f * (float)(j - 3) - 1.0f;
        float tj2 = 0.4f * (float)(j - 1) - 1.0f;
        b1[j] = (x - tj) * 2.5f * b0[j] + (tj2 - x) * 2.5f * b0[j + 1];
    }
    float b2[9];
#pragma unroll
    for (int j = 0; j < 9; j++) {
        float tj  = 0.4f * (float)(j - 3) - 1.0f;
        float tj3 = 0.4f * (float)(j)     - 1.0f;
        b2[j] = (x - tj) * 1.25f * b1[j] + (tj3 - x) * 1.25f * b1[j + 1];
    }
#pragma unroll
    for (int j = 0; j < 8; j++) {
        float tj  = 0.4f * (float)(j - 3) - 1.0f;
        float tj4 = 0.4f * (float)(j + 1) - 1.0f;
        bs[j] = (x - tj) * 0.83333333333f * b2[j] + (tj4 - x) * 0.83333333333f * b2[j + 1];
    }
}

__device__ __forceinline__ void bf_split(float v, __nv_bfloat16* ph, __nv_bfloat16* pl) {
    __nv_bfloat16 h = __float2bfloat16(v);
    *ph = h;
    *pl = __float2bfloat16(v - __bfloat162float(h));
}

// ---------------- PTX helpers (plain sm_80-class; valid on sm_103 target) --------
__device__ __forceinline__ uint32_t smem_u32(const void* p) {
    uint32_t a;
    asm("{ .reg .u64 t; cvta.to.shared.u64 t, %1; cvt.u32.u64 %0, t; }" : "=r"(a) : "l"(p));
    return a;
}
__device__ __forceinline__ void cp16(uint32_t dst, const void* src) {
    asm volatile("cp.async.cg.shared.global [%0], [%1], 16;" :: "r"(dst), "l"(src));
}
__device__ __forceinline__ void cp_commit() {
    asm volatile("cp.async.commit_group;" ::: "memory");
}
__device__ __forceinline__ void ldsm4(uint32_t* r, uint32_t addr) {
    asm volatile("ldmatrix.sync.aligned.m8n8.x4.shared.b16 {%0,%1,%2,%3}, [%4];"
                 : "=r"(r[0]), "=r"(r[1]), "=r"(r[2]), "=r"(r[3]) : "r"(addr));
}
__device__ __forceinline__ void mma16816(float* c, const uint32_t* a, uint32_t b0, uint32_t b1) {
    asm volatile("mma.sync.aligned.m16n8k16.row.col.f32.bf16.bf16.f32 "
                 "{%0,%1,%2,%3}, {%4,%5,%6,%7}, {%8,%9}, {%0,%1,%2,%3};"
                 : "+f"(c[0]), "+f"(c[1]), "+f"(c[2]), "+f"(c[3])
                 : "r"(a[0]), "r"(a[1]), "r"(a[2]), "r"(a[3]), "r"(b0), "r"(b1));
}

// ---------------- tensor-core GEMM: C[M,N] (+=) Ahl[M,K] @ Bhl[N,K]^T ----------------
// 128x128 CTA tile, 8 warps (4x2), K-chunk 64 bf16, double-buffered cp.async.
// bf16x3 emulated fp32: AhBh + AlBh + AhBl.
#define GEMM_SMEM 131072

template <int RESID>
__global__ __launch_bounds__(256, 1) void gemm_mma(const __nv_bfloat16* __restrict__ Ah,
                                                   const __nv_bfloat16* __restrict__ Al,
                                                   const __nv_bfloat16* __restrict__ Bh,
                                                   const __nv_bfloat16* __restrict__ Bl,
                                                   float* __restrict__ C, int N, int K) {
    extern __shared__ __align__(1024) char smem[];
    const uint32_t sb = smem_u32(smem);
    int tid = threadIdx.x, wid = tid >> 5, lane = tid & 31;
    int warp_m = wid & 3, warp_n = wid >> 2;      // 4x2 warp grid: 32 rows x 64 cols each
    int row0 = blockIdx.y * 128, col0 = blockIdx.x * 128;
    const int NC = K >> 6;

    float acc[2][8][4];
#pragma unroll
    for (int a = 0; a < 2; a++)
#pragma unroll
        for (int b = 0; b < 8; b++)
#pragma unroll
            for (int c = 0; c < 4; c++) acc[a][b][c] = 0.f;

    // global-load indices: 1024 16B-segments per operand array per chunk
    int gr = 0, gs = 0;
    {
        // thread t handles segs t, t+256, t+512, t+768 : row = idx>>3, seg = idx&7
    }

    // prologue: load chunk 0 into buffer 0
#pragma unroll
    for (int j = 0; j < 4; j++) {
        int idx = tid + j * 256;
        int r = idx >> 3, s = idx & 7;
        uint32_t off = (uint32_t)r * 128u + (uint32_t)s * 16u;
        uint32_t sw = off ^ ((off >> 3) & 0x70u);
        size_t ao = (size_t)(row0 + r) * K + s * 8;
        size_t bo = (size_t)(col0 + r) * K + s * 8;
        cp16(sb + 0u     + sw, Ah + ao);
        cp16(sb + 16384u + sw, Al + ao);
        cp16(sb + 32768u + sw, Bh + bo);
        cp16(sb + 49152u + sw, Bl + bo);
    }
    cp_commit();

    int lrow = lane & 15;            // ldmatrix row within 16
    int lk = (lane >> 4) << 4;       // 0 or 16 byte col offset

    for (int c = 0; c < NC; c++) {
        uint32_t buf = (uint32_t)(c & 1) * 65536u;
        if (c + 1 < NC) {
            uint32_t nbuf = (uint32_t)((c + 1) & 1) * 65536u;
            int k0 = (c + 1) << 6;
#pragma unroll
            for (int j = 0; j < 4; j++) {
                int idx = tid + j * 256;
                int r = idx >> 3, s = idx & 7;
                uint32_t off = (uint32_t)r * 128u + (uint32_t)s * 16u;
                uint32_t sw = off ^ ((off >> 3) & 0x70u);
                size_t ao = (size_t)(row0 + r) * K + k0 + s * 8;
                size_t bo = (size_t)(col0 + r) * K + k0 + s * 8;
                cp16(sb + nbuf + 0u     + sw, Ah + ao);
                cp16(sb + nbuf + 16384u + sw, Al + ao);
                cp16(sb + nbuf + 32768u + sw, Bh + bo);
                cp16(sb + nbuf + 49152u + sw, Bl + bo);
            }
            cp_commit();
            asm volatile("cp.async.wait_group 1;" ::: "memory");
        } else {
            asm volatile("cp.async.wait_group 0;" ::: "memory");
        }
        __syncthreads();

        uint32_t bAh = sb + buf, bAl = sb + buf + 16384u;
        uint32_t bBh = sb + buf + 32768u, bBl = sb + buf + 49152u;
#pragma unroll
        for (int k16 = 0; k16 < 4; k16++) {
            int koff = k16 * 32 + lk;
            uint32_t aH[2][4], aL[2][4], bH[4][4], bL[4][4];
#pragma unroll
            for (int mt = 0; mt < 2; mt++) {
                uint32_t off = (uint32_t)(warp_m * 32 + mt * 16 + lrow) * 128u + (uint32_t)koff;
                uint32_t sw = off ^ ((off >> 3) & 0x70u);
                ldsm4(aH[mt], bAh + sw);
                ldsm4(aL[mt], bAl + sw);
            }
#pragma unroll
            for (int np = 0; np < 4; np++) {
                uint32_t off = (uint32_t)(warp_n * 64 + np * 16 + lrow) * 128u + (uint32_t)koff;
                uint32_t sw = off ^ ((off >> 3) & 0x70u);
                ldsm4(bH[np], bBh + sw);
                ldsm4(bL[np], bBl + sw);
            }
#pragma unroll
            for (int mt = 0; mt < 2; mt++)
#pragma unroll
                for (int np = 0; np < 4; np++)
#pragma unroll
                    for (int hf = 0; hf < 2; hf++) {
                        int nt = np * 2 + hf;
                        mma16816(acc[mt][nt], aH[mt], bH[np][hf], bH[np][hf + 2]);
                        mma16816(acc[mt][nt], aL[mt], bH[np][hf], bH[np][hf + 2]);
                        mma16816(acc[mt][nt], aH[mt], bL[np][hf], bL[np][hf + 2]);
                    }
        }
        __syncthreads();
    }

    // epilogue
    int g = lane >> 2, t4 = lane & 3;
#pragma unroll
    for (int mt = 0; mt < 2; mt++) {
#pragma unroll
        for (int np = 0; np < 4; np++)
#pragma unroll
            for (int hf = 0; hf < 2; hf++) {
                int nt = np * 2 + hf;
                int rowa = row0 + warp_m * 32 + mt * 16 + g;
                int col = col0 + warp_n * 64 + np * 16 + hf * 8 + 2 * t4;
                float2* p0 = (float2*)&C[(size_t)rowa * N + col];
                float2* p1 = (float2*)&C[(size_t)(rowa + 8) * N + col];
                float2 v0 = make_float2(acc[mt][nt][0], acc[mt][nt][1]);
                float2 v1 = make_float2(acc[mt][nt][2], acc[mt][nt][3]);
                if (RESID) {
                    float2 o0 = *p0, o1 = *p1;
                    v0.x += o0.x; v0.y += o0.y;
                    v1.x += o1.x; v1.y += o1.y;
                }
                *p0 = v0;
                *p1 = v1;
            }
    }
}

// ---------------- operand prep ----------------
__global__ __launch_bounds__(256) void expand_kernel(const float* __restrict__ x,
                                                     __nv_bfloat16* __restrict__ Eh,
                                                     __nv_bfloat16* __restrict__ El) {
    int idx = blockIdx.x * 256 + threadIdx.x;          // over ROWS*DIN
    float v = x[idx];
    int row = idx / DIN, i = idx - row * DIN;
    float a[9];
    a[0] = fsilu(v);
    kan_basis(v, a + 1);
    size_t base = (size_t)row * KAN1K + (size_t)i * 9;
#pragma unroll
    for (int k = 0; k < 9; k++) bf_split(a[k], &Eh[base + k], &El[base + k]);
}

__global__ __launch_bounds__(256) void w1b_kernel(const float* __restrict__ bw,
                                                  const float* __restrict__ sw,
                                                  const float* __restrict__ ss,
                                                  __nv_bfloat16* __restrict__ Wh,
                                                  __nv_bfloat16* __restrict__ Wl) {
    int idx = blockIdx.x * 256 + threadIdx.x;          // over 256*6912
    int n = idx / KAN1K, k = idx - n * KAN1K;
    int i = k / 9, c = k - i * 9;
    float v;
    if (c == 0) v = bw[n * DIN + i];
    else        v = sw[(n * DIN + i) * 8 + (c - 1)] * ss[n * DIN + i];
    bf_split(v, &Wh[idx], &Wl[idx]);
}

__global__ __launch_bounds__(256) void cvt_kernel(const float* __restrict__ in,
                                                  __nv_bfloat16* __restrict__ h,
                                                  __nv_bfloat16* __restrict__ l) {
    int idx = blockIdx.x * 256 + threadIdx.x;
    bf_split(in[idx], &h[idx], &l[idx]);
}

__global__ __launch_bounds__(256) void xpad_kernel(const float* __restrict__ xw,
                                                   __nv_bfloat16* __restrict__ h,
                                                   __nv_bfloat16* __restrict__ l) {
    int idx = blockIdx.x * 256 + threadIdx.x;          // over NLAYER*SSMW*IDIM
    int layer = idx / (SSMW * IDIM);
    int rem = idx - layer * (SSMW * IDIM);
    int n = rem / IDIM, k = rem - n * IDIM;
    float v = (n < 48) ? xw[(layer * 48 + n) * IDIM + k] : 0.0f;
    bf_split(v, &h[idx], &l[idx]);
}

// ---------------- norms ----------------
__device__ __forceinline__ float block_sum256(float v, float* red) {
    int tid = threadIdx.x;
#pragma unroll
    for (int o = 16; o; o >>= 1) v += __shfl_xor_sync(0xffffffffu, v, o);
    if ((tid & 31) == 0) red[tid >> 5] = v;
    __syncthreads();
    if (tid < 32) {
        float t = (tid < 8) ? red[tid] : 0.f;
#pragma unroll
        for (int o = 4; o; o >>= 1) t += __shfl_xor_sync(0xffffffffu, t, o);
        if (tid == 0) red[0] = t;
    }
    __syncthreads();
    float r = red[0];
    __syncthreads();
    return r;
}

__global__ __launch_bounds__(256) void layernorm_kernel(float* __restrict__ H,
                                                        const float* __restrict__ g,
                                                        const float* __restrict__ b) {
    __shared__ float red[8];
    int row = blockIdx.x, tid = threadIdx.x;
    float v = H[row * HDIM + tid];
    float mean = block_sum256(v, red) * (1.0f / HDIM);
    float d = v - mean;
    float var = block_sum256(d * d, red) * (1.0f / HDIM);
    H[row * HDIM + tid] = d * rsqrtf(var + 1e-5f) * g[tid] + b[tid];
}

__global__ __launch_bounds__(256) void rmsnorm_bf_kernel(const float* __restrict__ In,
                                                         const float* __restrict__ w,
                                                         __nv_bfloat16* __restrict__ Oh,
                                                         __nv_bfloat16* __restrict__ Ol) {
    __shared__ float red[8];
    int row = blockIdx.x, tid = threadIdx.x;
    float v = In[row * HDIM + tid];
    float ms = block_sum256(v * v, red) * (1.0f / HDIM);
    float o = w[tid] * v * rsqrtf(ms + 1e-5f);
    bf_split(o, &Oh[row * HDIM + tid], &Ol[row * HDIM + tid]);
}

__global__ __launch_bounds__(256) void rmsnorm_kernel(const float* __restrict__ In,
                                                      const float* __restrict__ w,
                                                      float* __restrict__ Out) {
    __shared__ float red[8];
    int row = blockIdx.x, tid = threadIdx.x;
    float v = In[row * HDIM + tid];
    float ms = block_sum256(v * v, red) * (1.0f / HDIM);
    Out[row * HDIM + tid] = w[tid] * v * rsqrtf(ms + 1e-5f);
}

// ---------------- mamba pieces ----------------
__global__ __launch_bounds__(512) void conv_silu_kernel(const float* __restrict__ proj,
                                                        const float* __restrict__ cw,
                                                        const float* __restrict__ cb,
                                                        float* __restrict__ u,
                                                        __nv_bfloat16* __restrict__ uh,
                                                        __nv_bfloat16* __restrict__ ul) {
    int i = threadIdx.x;
    int bl = blockIdx.x;
    int b = bl >> 9, l = bl & 511;
    float acc = cb[i];
#pragma unroll
    for (int k = 0; k < KCONV; k++) {
        int ll = l - 3 + k;
        if (ll >= 0)
            acc = fmaf(proj[((b << 9) + ll) * (2 * IDIM) + i], cw[i * KCONV + k], acc);
    }
    float s = fsilu(acc);
    u[bl * IDIM + i] = s;
    bf_split(s, &uh[bl * IDIM + i], &ul[bl * IDIM + i]);
}

__global__ __launch_bounds__(256) void dt_kernel(const float* __restrict__ ssm,
                                                 const float* __restrict__ dtw,
                                                 const float* __restrict__ dtb,
                                                 float* __restrict__ dt) {
    int idx = blockIdx.x * 256 + threadIdx.x;
    int i = idx & (IDIM - 1);
    int row = idx >> 9;
    float z = dtb[i];
#pragma unroll
    for (int r = 0; r < RDIM; r++)
        z = fmaf(ssm[row * SSMW + r], dtw[i * RDIM + r], z);
    float sp = (z > 15.f) ? z : fln(1.0f + fexp(z));
    dt[idx] = sp;
}

__global__ __launch_bounds__(256) void scan_kernel(const float* __restrict__ dt,
                                                   const float* __restrict__ u,
                                                   const float* __restrict__ ssm,
                                                   const float* __restrict__ proj,
                                                   const float* __restrict__ alog,
                                                   const float* __restrict__ Dp,
                                                   __nv_bfloat16* __restrict__ yh,
                                                   __nv_bfloat16* __restrict__ yl) {
    int idx = blockIdx.x * 256 + threadIdx.x;
    int n = idx & 15;
    int ch = idx >> 4;
    int i = ch & (IDIM - 1);
    int b = ch >> 9;
    float A = -fexp(alog[i * NSTATE + n]);
    float Dv = Dp[i];
    float s = 0.f;
    int base = b * SEQ;
    for (int l = 0; l < SEQ; l++) {
        int row = base + l;
        float dtv = dt[row * IDIM + i];
        float uv = u[row * IDIM + i];
        float Bv = ssm[row * SSMW + 16 + n];
        float Cv = ssm[row * SSMW + 32 + n];
        float dA = fexp(dtv * A);
        s = fmaf(s, dA, dtv * uv * Bv);
        float part = s * Cv;
        part += __shfl_xor_sync(0xffffffffu, part, 8);
        part += __shfl_xor_sync(0xffffffffu, part, 4);
        part += __shfl_xor_sync(0xffffffffu, part, 2);
        part += __shfl_xor_sync(0xffffffffu, part, 1);
        if (n == 0) {
            float g = proj[row * (2 * IDIM) + IDIM + i];
            float yv = (part + uv * Dv) * fsilu(g);
            bf_split(yv, &yh[row * IDIM + i], &yl[row * IDIM + i]);
        }
    }
}

// ---------------- pooling + KAN head ----------------
__global__ __launch_bounds__(256) void pool_kernel(const float* __restrict__ xr,
                                                   float* __restrict__ emb) {
    int b = blockIdx.x, tid = threadIdx.x;
    float sm = 0.f, mx = -3.402823466e38f;
    for (int l = 0; l < SEQ; l++) {
        float v = xr[(b * SEQ + l) * HDIM + tid];
        sm += v;
        mx = fmaxf(mx, v);
    }
    emb[b * 512 + tid] = sm * (1.0f / SEQ);
    emb[b * 512 + 256 + tid] = mx;
}

__global__ __launch_bounds__(256) void kan2_kernel(const float* __restrict__ emb,
                                                   const float* __restrict__ bw,
                                                   const float* __restrict__ sw,
                                                   const float* __restrict__ ss,
                                                   float* __restrict__ logits) {
    __shared__ float red[2][256];
    int b = blockIdx.x, tid = threadIdx.x;
    float p0 = 0.f, p1 = 0.f;
#pragma unroll
    for (int t = 0; t < 2; t++) {
        int i = tid + t * 256;
        float x = emb[b * 512 + i];
        float sl = fsilu(x);
        float bs[8];
        kan_basis(x, bs);
        float a0 = sl * bw[i];
        float a1 = sl * bw[512 + i];
        float s0 = ss[i], s1 = ss[512 + i];
#pragma unroll
        for (int k = 0; k < 8; k++) {
            a0 = fmaf(bs[k] * s0, sw[i * 8 + k], a0);
            a1 = fmaf(bs[k] * s1, sw[(512 + i) * 8 + k], a1);
        }
        p0 += a0;
        p1 += a1;
    }
    red[0][tid] = p0;
    red[1][tid] = p1;
    __syncthreads();
    for (int s = 128; s > 0; s >>= 1) {
        if (tid < s) {
            red[0][tid] += red[0][tid + s];
            red[1][tid] += red[1][tid + s];
        }
        __syncthreads();
    }
    if (tid == 0) {
        logits[b * 2 + 0] = red[0][0];
        logits[b * 2 + 1] = red[1][0];
    }
}

// ---------------- launch ----------------
extern "C" void kernel_launch(void* const* d_in, const int* in_sizes, int n_in,
                              void* d_out, int out_size) {
    const float* x         = (const float*)d_in[0];
    const float* base_w1   = (const float*)d_in[1];
    const float* spline_w1 = (const float*)d_in[2];
    const float* spline_s1 = (const float*)d_in[3];
    const float* ln_g      = (const float*)d_in[4];
    const float* ln_b      = (const float*)d_in[5];
    const float* norm_w    = (const float*)d_in[6];
    const float* in_proj_w = (const float*)d_in[7];
    const float* conv_w    = (const float*)d_in[8];
    const float* conv_b    = (const float*)d_in[9];
    const float* x_proj_w  = (const float*)d_in[10];
    const float* dt_w      = (const float*)d_in[11];
    const float* dt_b      = (const float*)d_in[12];
    const float* A_log     = (const float*)d_in[13];
    const float* Dp        = (const float*)d_in[14];
    const float* out_proj_w= (const float*)d_in[15];
    const float* normf_w   = (const float*)d_in[16];
    const float* base_w2   = (const float*)d_in[17];
    const float* spline_w2 = (const float*)d_in[18];
    const float* spline_s2 = (const float*)d_in[19];
    float* out = (float*)d_out;

    cudaFuncSetAttribute(gemm_mma<0>, cudaFuncAttributeMaxDynamicSharedMemorySize, GEMM_SMEM);
    cudaFuncSetAttribute(gemm_mma<1>, cudaFuncAttributeMaxDynamicSharedMemorySize, GEMM_SMEM);

    float *p_h, *p_xr, *p_proj, *p_u, *p_dt, *p_ssm;
    __nv_bfloat16 *p_Eh, *p_El, *p_W1h, *p_W1l, *p_IPh, *p_IPl, *p_OPh, *p_OPl;
    __nv_bfloat16 *p_XPh, *p_XPl, *p_Xh, *p_Xl, *p_Uh, *p_Ul, *p_Yh, *p_Yl;
    cudaGetSymbolAddress((void**)&p_h, g_h);
    cudaGetSymbolAddress((void**)&p_xr, g_xr);
    cudaGetSymbolAddress((void**)&p_proj, g_proj);
    cudaGetSymbolAddress((void**)&p_u, g_u);
    cudaGetSymbolAddress((void**)&p_dt, g_dt);
    cudaGetSymbolAddress((void**)&p_ssm, g_ssm);
    cudaGetSymbolAddress((void**)&p_Eh, g_Eh);
    cudaGetSymbolAddress((void**)&p_El, g_El);
    cudaGetSymbolAddress((void**)&p_W1h, g_W1h);
    cudaGetSymbolAddress((void**)&p_W1l, g_W1l);
    cudaGetSymbolAddress((void**)&p_IPh, g_IPh);
    cudaGetSymbolAddress((void**)&p_IPl, g_IPl);
    cudaGetSymbolAddress((void**)&p_OPh, g_OPh);
    cudaGetSymbolAddress((void**)&p_OPl, g_OPl);
    cudaGetSymbolAddress((void**)&p_XPh, g_XPh);
    cudaGetSymbolAddress((void**)&p_XPl, g_XPl);
    cudaGetSymbolAddress((void**)&p_Xh, g_Xh);
    cudaGetSymbolAddress((void**)&p_Xl, g_Xl);
    cudaGetSymbolAddress((void**)&p_Uh, g_Uh);
    cudaGetSymbolAddress((void**)&p_Ul, g_Ul);
    cudaGetSymbolAddress((void**)&p_Yh, g_Yh);
    cudaGetSymbolAddress((void**)&p_Yl, g_Yl);

    // weight prep (hi/lo bf16)
    w1b_kernel<<<(HDIM * KAN1K) / 256, 256>>>(base_w1, spline_w1, spline_s1, p_W1h, p_W1l);
    cvt_kernel<<<(NLAYER * 2 * IDIM * HDIM) / 256, 256>>>(in_proj_w, p_IPh, p_IPl);
    cvt_kernel<<<(NLAYER * HDIM * IDIM) / 256, 256>>>(out_proj_w, p_OPh, p_OPl);
    xpad_kernel<<<(NLAYER * SSMW * IDIM) / 256, 256>>>(x_proj_w, p_XPh, p_XPl);

    // KAN1: expand activations, tensor GEMM, layernorm
    expand_kernel<<<(ROWS * DIN) / 256, 256>>>(x, p_Eh, p_El);
    gemm_mma<0><<<dim3(HDIM / 128, ROWS / 128), 256, GEMM_SMEM>>>(p_Eh, p_El, p_W1h, p_W1l, p_h, HDIM, KAN1K);
    layernorm_kernel<<<ROWS, 256>>>(p_h, ln_g, ln_b);

    // Mamba blocks
    for (int l = 0; l < NLAYER; l++) {
        rmsnorm_bf_kernel<<<ROWS, 256>>>(p_h, norm_w + l * HDIM, p_Xh, p_Xl);
        gemm_mma<0><<<dim3(2 * IDIM / 128, ROWS / 128), 256, GEMM_SMEM>>>(
            p_Xh, p_Xl, p_IPh + l * 2 * IDIM * HDIM, p_IPl + l * 2 * IDIM * HDIM,
            p_proj, 2 * IDIM, HDIM);
        conv_silu_kernel<<<ROWS, IDIM>>>(p_proj, conv_w + l * IDIM * KCONV,
                                         conv_b + l * IDIM, p_u, p_Uh, p_Ul);
        gemm_mma<0><<<dim3(1, ROWS / 128), 256, GEMM_SMEM>>>(
            p_Uh, p_Ul, p_XPh + l * SSMW * IDIM, p_XPl + l * SSMW * IDIM,
            p_ssm, SSMW, IDIM);
        dt_kernel<<<(ROWS * IDIM) / 256, 256>>>(p_ssm, dt_w + l * IDIM * RDIM,
                                                dt_b + l * IDIM, p_dt);
        scan_kernel<<<(BATCH * IDIM * NSTATE) / 256, 256>>>(
            p_dt, p_u, p_ssm, p_proj, A_log + l * IDIM * NSTATE, Dp + l * IDIM, p_Yh, p_Yl);
        gemm_mma<1><<<dim3(HDIM / 128, ROWS / 128), 256, GEMM_SMEM>>>(
            p_Yh, p_Yl, p_OPh + l * HDIM * IDIM, p_OPl + l * HDIM * IDIM,
            p_h, HDIM, IDIM);
    }

    // final norm, pool, head
    rmsnorm_kernel<<<ROWS, 256>>>(p_h, normf_w, p_xr);
    pool_kernel<<<BATCH, 256>>>(p_xr, out + 32);
    kan2_kernel<<<BATCH, 256>>>(out + 32, base_w2, spline_w2, spline_s2, out);
}